// round 4
// baseline (speedup 1.0000x reference)
#include <cuda_runtime.h>

// Problem constants
#define IN_DIM   225      // 15*15
#define NJ       28       // 7 scales * 4 hidden
#define NJ2      14       // NJ/2 (f32x2 pairs)
#define KC       9        // K-chunk size (odd -> stride-9 shared is conflict-free)
#define NCHUNK   25       // 225/9
#define THREADS  128
#define ROWS_PER_BLOCK 256  // 2 rows per thread

// Precomputed parameters (written by prep kernel each launch; deterministic)
__device__ __align__(16) float g_W1p[IN_DIM * NJ];  // W1 folded with scale, [k][j=s*4+h]
__device__ float g_V[NJ];             // 2^s * sum_k W2[s,h,k] / 28
__device__ float g_C;                 // sum_{s,k} 2^s * b2[s,k] / 28

typedef unsigned long long ull;

__device__ __forceinline__ ull pack2(float lo, float hi) {
    ull r; asm("mov.b64 %0,{%1,%2};" : "=l"(r) : "f"(lo), "f"(hi)); return r;
}
__device__ __forceinline__ void unpack2(ull v, float& lo, float& hi) {
    asm("mov.b64 {%0,%1},%2;" : "=f"(lo), "=f"(hi) : "l"(v));
}
__device__ __forceinline__ void fma2(ull& d, ull a, ull b) {
    asm("fma.rn.f32x2 %0,%1,%2,%0;" : "+l"(d) : "l"(a), "l"(b));
}

__device__ __forceinline__ float gelu_exact(float v) {
    return 0.5f * v * (1.0f + erff(v * 0.70710678118654752440f));
}
__device__ __forceinline__ float softplus_stable(float r) {
    return fmaxf(r, 0.0f) + log1pf(expf(-fabsf(r)));
}

// ---------------------------------------------------------------------------
// Prep: fold scales into W1, collapse layer-2 + /scale + mean into (V, C).
// ---------------------------------------------------------------------------
__global__ void prep_kernel(const float* __restrict__ W1,
                            const float* __restrict__ W2,
                            const float* __restrict__ b2) {
    int t = threadIdx.x;
    for (int i = t; i < IN_DIM * NJ; i += 256) {
        int k = i / NJ;
        int j = i - k * NJ;
        int s = j >> 2;
        int h = j & 3;
        // W1 layout: [s][k][h] = s*900 + k*4 + h ; scale = 2^-s
        g_W1p[i] = W1[s * (IN_DIM * 4) + k * 4 + h] * exp2f(-(float)s);
    }
    if (t < NJ) {
        int s = t >> 2, h = t & 3;
        float sum = 0.0f;
        #pragma unroll
        for (int k4 = 0; k4 < 4; ++k4) sum += W2[s * 16 + h * 4 + k4];
        g_V[t] = sum * exp2f((float)s) * (1.0f / 28.0f);
    }
    if (t == 0) {
        float c = 0.0f;
        for (int s = 0; s < 7; ++s) {
            float inv = exp2f((float)s);
            #pragma unroll
            for (int k4 = 0; k4 < 4; ++k4) c += b2[s * 4 + k4] * inv;
        }
        g_C = c * (1.0f / 28.0f);
    }
}

// ---------------------------------------------------------------------------
// Main: per-row 225x28 GEMM (f32x2 packed FMA) + GELU + fused reduction.
// 128 threads, 2 rows/thread; x staged in 9-wide K-chunks; weights via LDS.128.
// ---------------------------------------------------------------------------
__global__ __launch_bounds__(THREADS, 6)
void mlp_main_kernel(const float* __restrict__ x,
                     const float* __restrict__ b1,
                     float* __restrict__ out) {
    __shared__ __align__(16) float sw[IN_DIM * NJ];       // 25200 B
    __shared__ float sx[ROWS_PER_BLOCK * KC];             // 9216 B
    __shared__ float sV[NJ];
    __shared__ float sC;

    int tid = threadIdx.x;

    // Stage folded weights (vectorized: 6300 floats = 1575 float4)
    {
        const float4* src = (const float4*)g_W1p;
        float4* dst = (float4*)sw;
        #pragma unroll 4
        for (int i = tid; i < (IN_DIM * NJ) / 4; i += THREADS) dst[i] = src[i];
    }
    if (tid < NJ)  sV[tid] = g_V[tid];
    if (tid == 0)  sC = g_C;

    // Accumulators init = b1 (bias fold). Row A = base+tid, Row B = base+tid+128.
    ull accA[NJ2], accB[NJ2];
    #pragma unroll
    for (int j2 = 0; j2 < NJ2; ++j2) {
        float lo = b1[2 * j2], hi = b1[2 * j2 + 1];
        accA[j2] = pack2(lo, hi);
        accB[j2] = accA[j2];
    }

    int base = (int)blockIdx.x * ROWS_PER_BLOCK;
    const float* gx = x + (long long)base * IN_DIM;

    for (int c = 0; c < NCHUNK; ++c) {
        // Stage x chunk [256 rows][9 cols]
        __syncthreads();
        #pragma unroll
        for (int j = 0; j < (ROWS_PER_BLOCK * KC) / THREADS; ++j) {
            int i = j * THREADS + tid;
            int r = i / KC;
            int col = i - r * KC;
            sx[i] = gx[r * IN_DIM + c * KC + col];
        }
        __syncthreads();

        #pragma unroll
        for (int k = 0; k < KC; ++k) {
            float xA = sx[tid * KC + k];                      // stride 9: conflict-free
            float xB = sx[(tid + THREADS) * KC + k];
            ull pA = pack2(xA, xA);
            ull pB = pack2(xB, xB);
            // 7 x LDS.128 (broadcast): 112B of weights per k, 16B-aligned (112*k)
            const ulonglong2* w = (const ulonglong2*)(sw + (c * KC + k) * NJ);
            #pragma unroll
            for (int j4 = 0; j4 < 7; ++j4) {
                ulonglong2 wv = w[j4];
                fma2(accA[2 * j4],     pA, wv.x);
                fma2(accA[2 * j4 + 1], pA, wv.y);
                fma2(accB[2 * j4],     pB, wv.x);
                fma2(accB[2 * j4 + 1], pB, wv.y);
            }
        }
    }

    // Epilogue: exact GELU + fused (layer2 + /scale + mean) dot + softplus
    float rA = sC, rB = sC;
    #pragma unroll
    for (int j2 = 0; j2 < NJ2; ++j2) {
        float h0, h1;
        unpack2(accA[j2], h0, h1);
        rA += gelu_exact(h0) * sV[2 * j2] + gelu_exact(h1) * sV[2 * j2 + 1];
        unpack2(accB[j2], h0, h1);
        rB += gelu_exact(h0) * sV[2 * j2] + gelu_exact(h1) * sV[2 * j2 + 1];
    }
    out[base + tid]           = softplus_stable(rA);
    out[base + tid + THREADS] = softplus_stable(rB);
}

// ---------------------------------------------------------------------------
extern "C" void kernel_launch(void* const* d_in, const int* in_sizes, int n_in,
                              void* d_out, int out_size) {
    const float* x  = (const float*)d_in[0];
    const float* W1 = (const float*)d_in[1];
    const float* b1 = (const float*)d_in[2];
    const float* W2 = (const float*)d_in[3];
    const float* b2 = (const float*)d_in[4];
    float* out = (float*)d_out;

    prep_kernel<<<1, 256>>>(W1, W2, b2);

    int blocks = out_size / ROWS_PER_BLOCK;   // 262144/256 = 1024
    mlp_main_kernel<<<blocks, THREADS>>>(x, b1, out);
}

// round 6
// speedup vs baseline: 1.0087x; 1.0087x over previous
#include <cuda_runtime.h>
#include <cstdint>

// Problem constants
#define IN_DIM   225      // 15*15
#define NJ       28       // 7 scales * 4 hidden
#define NJ2      14       // NJ/2 (f32x2 pairs)
#define KC       9        // K-chunk size (odd -> stride-9 shared is conflict-free)
#define NCHUNK   25       // 225/9
#define THREADS  128
#define ROWS_PER_BLOCK 256  // 2 rows per thread
#define CHUNK_ELEMS (ROWS_PER_BLOCK * KC)   // 2304
#define ELEMS_PER_THREAD (CHUNK_ELEMS / THREADS)  // 18

// Precomputed parameters (written by prep kernel each launch; deterministic)
__device__ __align__(16) float g_W1p[IN_DIM * NJ];  // W1 folded with scale, [k][j=s*4+h]
__device__ float g_V[NJ];             // 2^s * sum_k W2[s,h,k] / 28
__device__ float g_C;                 // sum_{s,k} 2^s * b2[s,k] / 28

typedef unsigned long long ull;
typedef unsigned int u32;

__device__ __forceinline__ ull pack2(float lo, float hi) {
    ull r; asm("mov.b64 %0,{%1,%2};" : "=l"(r) : "f"(lo), "f"(hi)); return r;
}
__device__ __forceinline__ void unpack2(ull v, float& lo, float& hi) {
    asm("mov.b64 {%0,%1},%2;" : "=f"(lo), "=f"(hi) : "l"(v));
}
__device__ __forceinline__ void fma2(ull& d, ull a, ull b) {
    asm("fma.rn.f32x2 %0,%1,%2,%0;" : "+l"(d) : "l"(a), "l"(b));
}

__device__ __forceinline__ void cpa4(u32 dst_smem, const float* src) {
    asm volatile("cp.async.ca.shared.global [%0], [%1], 4;" :: "r"(dst_smem), "l"(src));
}
__device__ __forceinline__ void cpa16(u32 dst_smem, const float4* src) {
    asm volatile("cp.async.ca.shared.global [%0], [%1], 16;" :: "r"(dst_smem), "l"(src));
}
__device__ __forceinline__ void cpa_commit() {
    asm volatile("cp.async.commit_group;");
}
template<int N>
__device__ __forceinline__ void cpa_wait() {
    asm volatile("cp.async.wait_group %0;" :: "n"(N));
}

__device__ __forceinline__ float gelu_exact(float v) {
    return 0.5f * v * (1.0f + erff(v * 0.70710678118654752440f));
}
__device__ __forceinline__ float softplus_stable(float r) {
    return fmaxf(r, 0.0f) + log1pf(expf(-fabsf(r)));
}

// ---------------------------------------------------------------------------
// Prep: fold scales into W1, collapse layer-2 + /scale + mean into (V, C).
// ---------------------------------------------------------------------------
__global__ void prep_kernel(const float* __restrict__ W1,
                            const float* __restrict__ W2,
                            const float* __restrict__ b2) {
    int t = threadIdx.x;
    for (int i = t; i < IN_DIM * NJ; i += 256) {
        int k = i / NJ;
        int j = i - k * NJ;
        int s = j >> 2;
        int h = j & 3;
        g_W1p[i] = W1[s * (IN_DIM * 4) + k * 4 + h] * exp2f(-(float)s);
    }
    if (t < NJ) {
        int s = t >> 2, h = t & 3;
        float sum = 0.0f;
        #pragma unroll
        for (int k4 = 0; k4 < 4; ++k4) sum += W2[s * 16 + h * 4 + k4];
        g_V[t] = sum * exp2f((float)s) * (1.0f / 28.0f);
    }
    if (t == 0) {
        float c = 0.0f;
        for (int s = 0; s < 7; ++s) {
            float inv = exp2f((float)s);
            #pragma unroll
            for (int k4 = 0; k4 < 4; ++k4) c += b2[s * 4 + k4] * inv;
        }
        g_C = c * (1.0f / 28.0f);
    }
}

// ---------------------------------------------------------------------------
// Main: per-row 225x28 GEMM (f32x2 FMA), cp.async double-buffered x staging.
// ---------------------------------------------------------------------------
__global__ __launch_bounds__(THREADS, 5)
void mlp_main_kernel(const float* __restrict__ x,
                     const float* __restrict__ b1,
                     float* __restrict__ out) {
    __shared__ __align__(16) float sw[IN_DIM * NJ];          // 25200 B
    __shared__ __align__(16) float sx[2][CHUNK_ELEMS];       // 2 x 9216 B

    int tid = threadIdx.x;
    int base = (int)blockIdx.x * ROWS_PER_BLOCK;
    const float* gx = x + (long long)base * IN_DIM;

    u32 sw_s = (u32)__cvta_generic_to_shared(sw);
    u32 sx_s = (u32)__cvta_generic_to_shared(sx);

    // Per-thread staging cursor: element i = j*128 + tid -> (row, col) in [256 x 9].
    // Incremental update: i += 128  =>  row += 14, col += 2, wrap if col >= 9.
    int st_row0 = tid / KC;
    int st_col0 = tid - st_row0 * KC;

    // --- group 0: weights (16B cp.async) + x chunk 0 ---
    {
        #pragma unroll 4
        for (int i = tid; i < (IN_DIM * NJ) / 4; i += THREADS)
            cpa16(sw_s + i * 16, (const float4*)g_W1p + i);
        int row = st_row0, col = st_col0;
        u32 dst = sx_s + tid * 4;
        #pragma unroll
        for (int j = 0; j < ELEMS_PER_THREAD; ++j) {
            cpa4(dst, gx + row * IN_DIM + col);
            dst += THREADS * 4;
            row += 14; col += 2;
            if (col >= KC) { col -= KC; row += 1; }
        }
        cpa_commit();
    }

    // Accumulators init = b1 (bias fold). Row A = base+tid, Row B = base+tid+128.
    ull accA[NJ2], accB[NJ2];
    #pragma unroll
    for (int j2 = 0; j2 < NJ2; ++j2) {
        float lo = b1[2 * j2], hi = b1[2 * j2 + 1];
        accA[j2] = pack2(lo, hi);
        accB[j2] = accA[j2];
    }

    for (int c = 0; c < NCHUNK; ++c) {
        // Prefetch chunk c+1 into the other buffer
        if (c + 1 < NCHUNK) {
            int buf = (c + 1) & 1;
            int row = st_row0, col = st_col0;
            const float* src0 = gx + (c + 1) * KC;
            u32 dst = sx_s + (buf * CHUNK_ELEMS + tid) * 4;
            #pragma unroll
            for (int j = 0; j < ELEMS_PER_THREAD; ++j) {
                cpa4(dst, src0 + row * IN_DIM + col);
                dst += THREADS * 4;
                row += 14; col += 2;
                if (col >= KC) { col -= KC; row += 1; }
            }
            cpa_commit();
            cpa_wait<1>();   // chunk c (and weights, for c=0) complete
        } else {
            cpa_wait<0>();
        }
        __syncthreads();

        const float* xb = sx[c & 1];
        #pragma unroll
        for (int k = 0; k < KC; ++k) {
            float xA = xb[tid * KC + k];                      // stride 9: conflict-free
            float xB = xb[(tid + THREADS) * KC + k];
            ull pA = pack2(xA, xA);
            ull pB = pack2(xB, xB);
            const ulonglong2* w = (const ulonglong2*)(sw + (c * KC + k) * NJ);
            #pragma unroll
            for (int j4 = 0; j4 < 7; ++j4) {
                ulonglong2 wv = w[j4];
                fma2(accA[2 * j4],     pA, wv.x);
                fma2(accA[2 * j4 + 1], pA, wv.y);
                fma2(accB[2 * j4],     pB, wv.x);
                fma2(accB[2 * j4 + 1], pB, wv.y);
            }
        }
        __syncthreads();   // protect buffer (c&1) from being overwritten by stage(c+2)
    }

    // Epilogue: exact GELU + fused (layer2 + /scale + mean) dot + softplus
    float rA = g_C, rB = g_C;
    #pragma unroll
    for (int j2 = 0; j2 < NJ2; ++j2) {
        float v0 = g_V[2 * j2], v1 = g_V[2 * j2 + 1];
        float h0, h1;
        unpack2(accA[j2], h0, h1);
        rA += gelu_exact(h0) * v0 + gelu_exact(h1) * v1;
        unpack2(accB[j2], h0, h1);
        rB += gelu_exact(h0) * v0 + gelu_exact(h1) * v1;
    }
    out[base + tid]           = softplus_stable(rA);
    out[base + tid + THREADS] = softplus_stable(rB);
}

// ---------------------------------------------------------------------------
extern "C" void kernel_launch(void* const* d_in, const int* in_sizes, int n_in,
                              void* d_out, int out_size) {
    const float* x  = (const float*)d_in[0];
    const float* W1 = (const float*)d_in[1];
    const float* b1 = (const float*)d_in[2];
    const float* W2 = (const float*)d_in[3];
    const float* b2 = (const float*)d_in[4];
    float* out = (float*)d_out;

    prep_kernel<<<1, 256>>>(W1, W2, b2);

    int blocks = out_size / ROWS_PER_BLOCK;   // 262144/256 = 1024
    mlp_main_kernel<<<blocks, THREADS>>>(x, b1, out);
}